// round 11
// baseline (speedup 1.0000x reference)
#include <cuda_runtime.h>
#include <cuda_bf16.h>
#include <cstdint>
#include <math.h>

#define NB   2048
#define NH   512
#define N4H  2048
#define NA   8
#define NZ   64
#define NT   64
#define TPB  512

// 2-stage ring, K=64 per chunk. Stage: AH 16K | AL 16K | BH 32K | BL 32K = 96KB
#define SA_AH 0
#define SA_AL 16384
#define SA_BH 32768
#define SA_BL 65536
#define STAGE_SZ  98304
#define SMEM_TOTAL (2 * STAGE_SZ)    // 196608

#define SWZ(o) ((o) ^ ((((unsigned)(o)) >> 3) & 0x70))

// ---- device scratch ----
__device__ float          g_xproj[NB * N4H];
__device__ float          g_xpP[(size_t)128 * 512 * 64];  // 64 floats per (cta,tid)
__device__ __nv_bfloat16  g_WbH[N4H * NH];
__device__ __nv_bfloat16  g_WbL[N4H * NH];
__device__ __nv_bfloat16  g_hbH[2][NB * NH];
__device__ __nv_bfloat16  g_hbL[2][NB * NH];
__device__ float          g_hist[(size_t)NT * NB * NH];

// ================= PTX helpers =================
__device__ __forceinline__ uint32_t smem_u32(const void* p) {
    uint32_t a;
    asm("{ .reg .u64 t; cvta.to.shared.u64 t, %1; cvt.u32.u64 %0, t; }" : "=r"(a) : "l"(p));
    return a;
}
__device__ __forceinline__ void cp16(uint32_t dst, const void* src) {
    asm volatile("cp.async.cg.shared.global [%0], [%1], 16;" :: "r"(dst), "l"(src) : "memory");
}
#define CP_COMMIT() asm volatile("cp.async.commit_group;" ::: "memory")
#define CP_WAIT1()  asm volatile("cp.async.wait_group 1;"  ::: "memory")
#define CP_WAIT0()  asm volatile("cp.async.wait_group 0;"  ::: "memory")
#define CLUSTER_SYNC() do { \
    asm volatile("barrier.cluster.arrive.aligned;" ::: "memory"); \
    asm volatile("barrier.cluster.wait.aligned;"   ::: "memory"); } while (0)

#define LDM_X4(r, ad) \
    asm volatile("ldmatrix.sync.aligned.m8n8.x4.shared.b16 {%0,%1,%2,%3}, [%4];" \
        : "=r"((r)[0]), "=r"((r)[1]), "=r"((r)[2]), "=r"((r)[3]) : "r"(ad))

#define MMA_BF16(d, a, b0, b1) \
    asm volatile("mma.sync.aligned.m16n8k16.row.col.f32.bf16.bf16.f32 " \
        "{%0,%1,%2,%3}, {%4,%5,%6,%7}, {%8,%9}, {%0,%1,%2,%3};" \
        : "+f"((d)[0]), "+f"((d)[1]), "+f"((d)[2]), "+f"((d)[3]) \
        : "r"((a)[0]), "r"((a)[1]), "r"((a)[2]), "r"((a)[3]), "r"(b0), "r"(b1))

__device__ __forceinline__ float sigx(float x)  { return __fdividef(1.0f, 1.0f + __expf(-x)); }
__device__ __forceinline__ float tanhx(float x) { return __fdividef(2.0f, 1.0f + __expf(-2.0f * x)) - 1.0f; }
__device__ __forceinline__ uint32_t pack_bf2(float a, float b) {
    __nv_bfloat162 t = __floats2bfloat162_rn(a, b);
    return *(uint32_t*)&t;
}

// ================= prep kernels =================
__global__ __launch_bounds__(256, 1)
void xproj_kernel(const float* __restrict__ z, const float* __restrict__ Wih,
                  const float* __restrict__ bih, const float* __restrict__ bhh)
{
    const int j  = blockIdx.x * 256 + threadIdx.x;
    const int b0 = blockIdx.y * 16;
    __shared__ float zs[16][64];
    for (int i = threadIdx.x; i < 16 * 64; i += 256)
        zs[i >> 6][i & 63] = z[(b0 + (i >> 6)) * NZ + (i & 63)];
    __syncthreads();
    float w[64];
#pragma unroll
    for (int k4 = 0; k4 < 16; k4++) {
        float4 v = *(const float4*)&Wih[j * (NA + NZ) + NA + k4 * 4];
        w[k4*4+0] = v.x; w[k4*4+1] = v.y; w[k4*4+2] = v.z; w[k4*4+3] = v.w;
    }
    const float bias = bih[j] + bhh[j];
#pragma unroll
    for (int bb = 0; bb < 16; bb++) {
        float acc = bias;
#pragma unroll
        for (int k = 0; k < 64; k++) acc += zs[bb][k] * w[k];
        g_xproj[(size_t)(b0 + bb) * N4H + j] = acc;
    }
}

// pack x_proj per (cta,tid) in accumulator-init order: 64 floats/thread (TPB=512 layout)
__global__ __launch_bounds__(512, 1)
void xpack_kernel()
{
    const int cta = blockIdx.x, tid = threadIdx.x;
    const int rank = cta & 7, brow0 = (cta >> 3) * 128;
    const int lane = tid & 31, wid = tid >> 5;
    const int wm = wid & 3, u0w = (wid >> 2) * 16;
    const int frow = lane >> 2, fcol = (lane & 3) * 2;
    float* dst = g_xpP + ((size_t)cta * 512 + tid) * 64;
    int idx = 0;
#pragma unroll
    for (int i = 0; i < 2; i++)
#pragma unroll
        for (int eh = 0; eh < 2; eh++) {
            const int b = brow0 + wm * 32 + i * 16 + frow + eh * 8;
#pragma unroll
            for (int g = 0; g < 4; g++)
#pragma unroll
                for (int u8 = 0; u8 < 2; u8++) {
                    const int col = g * 512 + rank * 64 + u0w + u8 * 8 + fcol;
                    dst[idx++] = g_xproj[(size_t)b * N4H + col];
                    dst[idx++] = g_xproj[(size_t)b * N4H + col + 1];
                }
        }
}

__global__ __launch_bounds__(256, 1)
void wsplit_kernel(const float* __restrict__ Whh)
{
    const int g = blockIdx.x * 256 + threadIdx.x;
    const int p = g >> 9, k = g & 511;
    const int orow = ((p >> 6) & 3) * 512 + (p >> 8) * 64 + (p & 63);
    float w = Whh[(size_t)orow * NH + k];
    __nv_bfloat16 hi = __float2bfloat16(w);
    __nv_bfloat16 lo = __float2bfloat16(w - __bfloat162float(hi));
    g_WbH[g] = hi; g_WbL[g] = lo;
}

__global__ __launch_bounds__(256, 1)
void zeroh_kernel()
{
    const int i = blockIdx.x * 256 + threadIdx.x;
    ((uint32_t*)&g_hbH[0][0])[i] = 0;
    ((uint32_t*)&g_hbL[0][0])[i] = 0;
}

__global__ __launch_bounds__(128, 1)
void outproj_kernel(const float* __restrict__ Wout, const float* __restrict__ bout,
                    float* __restrict__ out)
{
    __shared__ float hs[16][516];
    const int tid = threadIdx.x;
    const size_t r0 = (size_t)blockIdx.x * 16;
    const float4* src = (const float4*)&g_hist[r0 * NH];
    for (int i = tid; i < 16 * 128; i += 128) {
        float4 v = src[i];
        *(float4*)&hs[i >> 7][(i & 127) * 4] = v;
    }
    __syncthreads();
    const int r = tid >> 3, a = tid & 7;
    float s = bout[a];
    const float* hp = hs[r];
#pragma unroll 4
    for (int u4 = 0; u4 < 128; u4++) {
        float4 wq = __ldg((const float4*)&Wout[a * NH + u4 * 4]);
        float4 hq = *(const float4*)&hp[u4 * 4];
        s += hq.x * wq.x + hq.y * wq.y + hq.z * wq.z + hq.w * wq.w;
    }
    const size_t row = r0 + r;
    const int t = (int)(row >> 11), b = (int)(row & 2047);
    out[((size_t)b * NT + t) * NA + a] = s;
}

// ================= main LSTM kernel (512 threads, no spills) =================
extern __shared__ char dsm[];

__global__ __launch_bounds__(TPB, 1) __cluster_dims__(8, 1, 1)
void lstm_mma_kernel()
{
    const uint32_t sb = smem_u32(dsm);
    const int tid  = threadIdx.x;
    const int lane = tid & 31;
    const int wid  = tid >> 5;
    const int wm   = wid & 3;          // M block of 32 rows
    const int u0w  = (wid >> 2) * 16;  // u block of 16
    const int rank  = blockIdx.x & 7;
    const int brow0 = (blockIdx.x >> 3) * 128;
    const int frow = lane >> 2;
    const int fcol = (lane & 3) * 2;

    float acc[2][8][4];
    float cst[2][2][4];
#pragma unroll
    for (int i = 0; i < 2; i++)
#pragma unroll
        for (int u8 = 0; u8 < 2; u8++)
#pragma unroll
            for (int e = 0; e < 4; e++) cst[i][u8][e] = 0.0f;

    const char* Wbase_H = (const char*)g_WbH + (size_t)rank * 256 * 1024;
    const char* Wbase_L = (const char*)g_WbL + (size_t)rank * 256 * 1024;

// A: 16KB hi+lo -> 2 cp16/thread each; B: 32KB hi+lo -> 4/thread each (512 thr)
#define LOAD_CHUNK(kc, sbuf, AHp, ALp) { \
    const uint32_t stg = sb + (sbuf) * STAGE_SZ; \
    _Pragma("unroll") \
    for (int ii = 0; ii < 2; ii++) { \
        int q = tid + ii * 512, row = q >> 3, c16 = (q & 7) * 16; \
        uint32_t sw = SWZ(row * 128 + c16); \
        size_t so = (size_t)row * 1024 + (size_t)(kc) * 128 + c16; \
        cp16(stg + SA_AH + sw, (AHp) + so); \
        cp16(stg + SA_AL + sw, (ALp) + so); \
    } \
    _Pragma("unroll") \
    for (int ii = 0; ii < 4; ii++) { \
        int q = tid + ii * 512, row = q >> 3, c16 = (q & 7) * 16; \
        uint32_t sw = SWZ(row * 128 + c16); \
        size_t so = (size_t)row * 1024 + (size_t)(kc) * 128 + c16; \
        cp16(stg + SA_BH + sw, Wbase_H + so); \
        cp16(stg + SA_BL + sw, Wbase_L + so); \
    } }

#define COMPUTE_CHUNK(sbuf) { \
    const uint32_t stg = sb + (sbuf) * STAGE_SZ; \
    _Pragma("unroll") \
    for (int s = 0; s < 4; s++) { \
        uint32_t Ah[2][4], Al[2][4]; \
        _Pragma("unroll") \
        for (int i = 0; i < 2; i++) { \
            const int row = wm * 32 + i * 16 + (lane & 15); \
            const int kb  = s * 32 + ((lane >> 4) << 4); \
            const uint32_t sw = SWZ(row * 128 + kb); \
            LDM_X4(Ah[i], stg + SA_AH + sw); \
            LDM_X4(Al[i], stg + SA_AL + sw); \
        } \
        _Pragma("unroll") \
        for (int g = 0; g < 4; g++) { \
            uint32_t Bh[4], Bl[4]; \
            const int n  = g * 64 + u0w + ((lane >> 4) << 3) + (lane & 7); \
            const int kb = s * 32 + (((lane >> 3) & 1) << 4); \
            const uint32_t sw = SWZ(n * 128 + kb); \
            LDM_X4(Bh, stg + SA_BH + sw); \
            LDM_X4(Bl, stg + SA_BL + sw); \
            _Pragma("unroll") \
            for (int i = 0; i < 2; i++) { \
                MMA_BF16(acc[i][g * 2 + 0], Ah[i], Bh[0], Bh[1]); \
                MMA_BF16(acc[i][g * 2 + 1], Ah[i], Bh[2], Bh[3]); \
            } \
            _Pragma("unroll") \
            for (int i = 0; i < 2; i++) { \
                MMA_BF16(acc[i][g * 2 + 0], Al[i], Bh[0], Bh[1]); \
                MMA_BF16(acc[i][g * 2 + 1], Al[i], Bh[2], Bh[3]); \
            } \
            _Pragma("unroll") \
            for (int i = 0; i < 2; i++) { \
                MMA_BF16(acc[i][g * 2 + 0], Ah[i], Bl[0], Bl[1]); \
                MMA_BF16(acc[i][g * 2 + 1], Ah[i], Bl[2], Bl[3]); \
            } \
        } \
    } }

    for (int t = 0; t < NT; t++) {
        const int hb = t & 1, nb = hb ^ 1;
        const char* A_H = (const char*)g_hbH[hb] + (size_t)brow0 * 1024;
        const char* A_L = (const char*)g_hbL[hb] + (size_t)brow0 * 1024;

        LOAD_CHUNK(0, 0, A_H, A_L);
        CP_COMMIT();

        // accumulator init from packed x_proj (overlaps chunk-0 load)
        {
            const float4* xp = (const float4*)(g_xpP + ((size_t)blockIdx.x * 512 + tid) * 64);
#pragma unroll
            for (int ie = 0; ie < 4; ie++) {
                const int i = ie >> 1, e0 = (ie & 1) * 2;
#pragma unroll
                for (int g = 0; g < 4; g++) {
                    float4 v = __ldg(&xp[ie * 4 + g]);
                    acc[i][g * 2 + 0][e0]     = v.x;
                    acc[i][g * 2 + 0][e0 + 1] = v.y;
                    acc[i][g * 2 + 1][e0]     = v.z;
                    acc[i][g * 2 + 1][e0 + 1] = v.w;
                }
            }
        }

        for (int kc = 0; kc < 8; kc++) {
            if (kc < 7) { LOAD_CHUNK(kc + 1, (kc + 1) & 1, A_H, A_L); CP_COMMIT(); }
            if (kc < 7) CP_WAIT1(); else CP_WAIT0();
            __syncthreads();
            COMPUTE_CHUNK(kc & 1);
            __syncthreads();
        }

        // ---- epilogue ----
#pragma unroll
        for (int i = 0; i < 2; i++)
#pragma unroll
            for (int eh = 0; eh < 2; eh++) {
                const int b = brow0 + wm * 32 + i * 16 + frow + eh * 8;
                const int U = rank * 64 + u0w + fcol;
#pragma unroll
                for (int u8 = 0; u8 < 2; u8++) {
                    float h2[2];
#pragma unroll
                    for (int p = 0; p < 2; p++) {
                        const int e = eh * 2 + p;
                        float iv = sigx (acc[i][0 + u8][e]);
                        float fv = sigx (acc[i][2 + u8][e]);
                        float gv = tanhx(acc[i][4 + u8][e]);
                        float ov = sigx (acc[i][6 + u8][e]);
                        float cc = fv * cst[i][u8][e] + iv * gv;
                        cst[i][u8][e] = cc;
                        h2[p] = ov * tanhx(cc);
                    }
                    const int Uu = U + u8 * 8;
                    *(float2*)&g_hist[((size_t)t * NB + b) * NH + Uu] =
                        make_float2(h2[0], h2[1]);
                    float l0 = h2[0] - __bfloat162float(__float2bfloat16(h2[0]));
                    float l1 = h2[1] - __bfloat162float(__float2bfloat16(h2[1]));
                    *(uint32_t*)((char*)g_hbH[nb] + (size_t)b * 1024 + Uu * 2) =
                        pack_bf2(h2[0], h2[1]);
                    *(uint32_t*)((char*)g_hbL[nb] + (size_t)b * 1024 + Uu * 2) =
                        pack_bf2(l0, l1);
                }
            }

        __threadfence();
        CLUSTER_SYNC();
    }
#undef LOAD_CHUNK
#undef COMPUTE_CHUNK
}

// ---------------------------------------------------------------------------
// Inputs: z, W_ih, W_hh, b_ih, b_hh, W_out, b_out, seq_len
// ---------------------------------------------------------------------------
extern "C" void kernel_launch(void* const* d_in, const int* in_sizes, int n_in,
                              void* d_out, int out_size)
{
    (void)in_sizes; (void)n_in; (void)out_size;
    const float* z    = (const float*)d_in[0];
    const float* Wih  = (const float*)d_in[1];
    const float* Whh  = (const float*)d_in[2];
    const float* bih  = (const float*)d_in[3];
    const float* bhh  = (const float*)d_in[4];
    const float* Wout = (const float*)d_in[5];
    const float* bout = (const float*)d_in[6];
    float* out = (float*)d_out;

    zeroh_kernel <<<2048, 256>>>();
    xproj_kernel <<<dim3(N4H / 256, NB / 16), 256>>>(z, Wih, bih, bhh);
    xpack_kernel <<<128, 512>>>();
    wsplit_kernel<<<(N4H * NH) / 256, 256>>>(Whh);

    cudaFuncSetAttribute(lstm_mma_kernel, cudaFuncAttributeMaxDynamicSharedMemorySize,
                         SMEM_TOTAL);
    lstm_mma_kernel<<<128, TPB, SMEM_TOTAL>>>();

    outproj_kernel<<<(NT * NB) / 16, 128>>>(Wout, bout, out);
}

// round 12
// speedup vs baseline: 1.2574x; 1.2574x over previous
#include <cuda_runtime.h>
#include <cuda_fp16.h>
#include <cstdint>
#include <math.h>

#define NB   2048
#define NH   512
#define N4H  2048
#define NA   8
#define NZ   64
#define NT   64
#define TPB  512

// 2-stage ring, K=64 per chunk. Stage: AH 16K | AL 16K | B 32K = 64KB
#define SA_AH 0
#define SA_AL 16384
#define SA_B  32768
#define STAGE_SZ  65536
#define SMEM_TOTAL (2 * STAGE_SZ)    // 131072

#define SWZ(o) ((o) ^ ((((unsigned)(o)) >> 3) & 0x70))

// ---- device scratch ----
__device__ float  g_xproj[NB * N4H];
__device__ float  g_xpP[(size_t)128 * 512 * 64];   // 64 floats per (cta,tid)
__device__ __half g_Wh[N4H * NH];                  // permuted W_hh, fp16
__device__ __half g_hbH[2][NB * NH];               // h hi (fp16) ping-pong
__device__ __half g_hbL[2][NB * NH];               // h lo (fp16) ping-pong
__device__ float  g_hist[(size_t)NT * NB * NH];

// ================= PTX helpers =================
__device__ __forceinline__ uint32_t smem_u32(const void* p) {
    uint32_t a;
    asm("{ .reg .u64 t; cvta.to.shared.u64 t, %1; cvt.u32.u64 %0, t; }" : "=r"(a) : "l"(p));
    return a;
}
__device__ __forceinline__ void cp16(uint32_t dst, const void* src) {
    asm volatile("cp.async.cg.shared.global [%0], [%1], 16;" :: "r"(dst), "l"(src) : "memory");
}
#define CP_COMMIT() asm volatile("cp.async.commit_group;" ::: "memory")
#define CP_WAIT1()  asm volatile("cp.async.wait_group 1;"  ::: "memory")
#define CP_WAIT0()  asm volatile("cp.async.wait_group 0;"  ::: "memory")
#define CLUSTER_SYNC() do { \
    asm volatile("barrier.cluster.arrive.aligned;" ::: "memory"); \
    asm volatile("barrier.cluster.wait.aligned;"   ::: "memory"); } while (0)

#define LDM_X4(r, ad) \
    asm volatile("ldmatrix.sync.aligned.m8n8.x4.shared.b16 {%0,%1,%2,%3}, [%4];" \
        : "=r"((r)[0]), "=r"((r)[1]), "=r"((r)[2]), "=r"((r)[3]) : "r"(ad))

#define MMA_F16(d, a, b0, b1) \
    asm volatile("mma.sync.aligned.m16n8k16.row.col.f32.f16.f16.f32 " \
        "{%0,%1,%2,%3}, {%4,%5,%6,%7}, {%8,%9}, {%0,%1,%2,%3};" \
        : "+f"((d)[0]), "+f"((d)[1]), "+f"((d)[2]), "+f"((d)[3]) \
        : "r"((a)[0]), "r"((a)[1]), "r"((a)[2]), "r"((a)[3]), "r"(b0), "r"(b1))

__device__ __forceinline__ float sigx(float x)  { return __fdividef(1.0f, 1.0f + __expf(-x)); }
__device__ __forceinline__ float tanhx(float x) { return __fdividef(2.0f, 1.0f + __expf(-2.0f * x)) - 1.0f; }
__device__ __forceinline__ uint32_t pack_h2(float a, float b) {
    __half2 t = __floats2half2_rn(a, b);
    return *(uint32_t*)&t;
}

// ================= prep kernels =================
__global__ __launch_bounds__(256, 1)
void xproj_kernel(const float* __restrict__ z, const float* __restrict__ Wih,
                  const float* __restrict__ bih, const float* __restrict__ bhh)
{
    const int j  = blockIdx.x * 256 + threadIdx.x;
    const int b0 = blockIdx.y * 16;
    __shared__ float zs[16][64];
    for (int i = threadIdx.x; i < 16 * 64; i += 256)
        zs[i >> 6][i & 63] = z[(b0 + (i >> 6)) * NZ + (i & 63)];
    __syncthreads();
    float w[64];
#pragma unroll
    for (int k4 = 0; k4 < 16; k4++) {
        float4 v = *(const float4*)&Wih[j * (NA + NZ) + NA + k4 * 4];
        w[k4*4+0] = v.x; w[k4*4+1] = v.y; w[k4*4+2] = v.z; w[k4*4+3] = v.w;
    }
    const float bias = bih[j] + bhh[j];
#pragma unroll
    for (int bb = 0; bb < 16; bb++) {
        float acc = bias;
#pragma unroll
        for (int k = 0; k < 64; k++) acc += zs[bb][k] * w[k];
        g_xproj[(size_t)(b0 + bb) * N4H + j] = acc;
    }
}

// pack x_proj per (cta,tid) in accumulator-init order + zero h buffers
__global__ __launch_bounds__(512, 1)
void xpack_kernel()
{
    const int cta = blockIdx.x, tid = threadIdx.x;
    const int rank = cta & 7, brow0 = (cta >> 3) * 128;
    const int lane = tid & 31, wid = tid >> 5;
    const int wm = wid & 3, u0w = (wid >> 2) * 16;
    const int frow = lane >> 2, fcol = (lane & 3) * 2;
    float* dst = g_xpP + ((size_t)cta * 512 + tid) * 64;
    int idx = 0;
#pragma unroll
    for (int i = 0; i < 2; i++)
#pragma unroll
        for (int eh = 0; eh < 2; eh++) {
            const int b = brow0 + wm * 32 + i * 16 + frow + eh * 8;
#pragma unroll
            for (int g = 0; g < 4; g++)
#pragma unroll
                for (int u8 = 0; u8 < 2; u8++) {
                    const int col = g * 512 + rank * 64 + u0w + u8 * 8 + fcol;
                    dst[idx++] = g_xproj[(size_t)b * N4H + col];
                    dst[idx++] = g_xproj[(size_t)b * N4H + col + 1];
                }
        }
    // zero h ping-pong buffer 0 (hi+lo): 512K u32 each, 65536 threads -> 8 each
    const int gt = cta * 512 + tid;
#pragma unroll
    for (int r = 0; r < 8; r++) {
        ((uint32_t*)&g_hbH[0][0])[gt + r * 65536] = 0;
        ((uint32_t*)&g_hbL[0][0])[gt + r * 65536] = 0;
    }
}

// W -> fp16 with row permutation: p = rank*256 + gate*64 + jj
__global__ __launch_bounds__(256, 1)
void whalf_kernel(const float* __restrict__ Whh)
{
    const int g = blockIdx.x * 256 + threadIdx.x;
    const int p = g >> 9, k = g & 511;
    const int orow = ((p >> 6) & 3) * 512 + (p >> 8) * 64 + (p & 63);
    g_Wh[g] = __float2half_rn(Whh[(size_t)orow * NH + k]);
}

__global__ __launch_bounds__(128, 1)
void outproj_kernel(const float* __restrict__ Wout, const float* __restrict__ bout,
                    float* __restrict__ out)
{
    __shared__ float hs[16][516];
    const int tid = threadIdx.x;
    const size_t r0 = (size_t)blockIdx.x * 16;
    const float4* src = (const float4*)&g_hist[r0 * NH];
    for (int i = tid; i < 16 * 128; i += 128) {
        float4 v = src[i];
        *(float4*)&hs[i >> 7][(i & 127) * 4] = v;
    }
    __syncthreads();
    const int r = tid >> 3, a = tid & 7;
    float s = bout[a];
    const float* hp = hs[r];
#pragma unroll 4
    for (int u4 = 0; u4 < 128; u4++) {
        float4 wq = __ldg((const float4*)&Wout[a * NH + u4 * 4]);
        float4 hq = *(const float4*)&hp[u4 * 4];
        s += hq.x * wq.x + hq.y * wq.y + hq.z * wq.z + hq.w * wq.w;
    }
    const size_t row = r0 + r;
    const int t = (int)(row >> 11), b = (int)(row & 2047);
    out[((size_t)b * NT + t) * NA + a] = s;
}

// ================= main LSTM kernel (fp16 2-pass) =================
extern __shared__ char dsm[];

__global__ __launch_bounds__(TPB, 1) __cluster_dims__(8, 1, 1)
void lstm_mma_kernel()
{
    const uint32_t sb = smem_u32(dsm);
    const int tid  = threadIdx.x;
    const int lane = tid & 31;
    const int wid  = tid >> 5;
    const int wm   = wid & 3;          // M block of 32 rows
    const int u0w  = (wid >> 2) * 16;  // u block of 16
    const int rank  = blockIdx.x & 7;
    const int brow0 = (blockIdx.x >> 3) * 128;
    const int frow = lane >> 2;
    const int fcol = (lane & 3) * 2;

    float acc[2][8][4];
    float cst[2][2][4];
#pragma unroll
    for (int i = 0; i < 2; i++)
#pragma unroll
        for (int u8 = 0; u8 < 2; u8++)
#pragma unroll
            for (int e = 0; e < 4; e++) cst[i][u8][e] = 0.0f;

    const char* Wbase = (const char*)g_Wh + (size_t)rank * 256 * 1024;

// A: 16KB hi + 16KB lo -> 2+2 cp16/thread; B: 32KB -> 4/thread (512 thr)
#define LOAD_CHUNK(kc, sbuf, AHp, ALp) { \
    const uint32_t stg = sb + (sbuf) * STAGE_SZ; \
    _Pragma("unroll") \
    for (int ii = 0; ii < 2; ii++) { \
        int q = tid + ii * 512, row = q >> 3, c16 = (q & 7) * 16; \
        uint32_t sw = SWZ(row * 128 + c16); \
        size_t so = (size_t)row * 1024 + (size_t)(kc) * 128 + c16; \
        cp16(stg + SA_AH + sw, (AHp) + so); \
        cp16(stg + SA_AL + sw, (ALp) + so); \
    } \
    _Pragma("unroll") \
    for (int ii = 0; ii < 4; ii++) { \
        int q = tid + ii * 512, row = q >> 3, c16 = (q & 7) * 16; \
        uint32_t sw = SWZ(row * 128 + c16); \
        size_t so = (size_t)row * 1024 + (size_t)(kc) * 128 + c16; \
        cp16(stg + SA_B + sw, Wbase + so); \
    } }

#define COMPUTE_CHUNK(sbuf) { \
    const uint32_t stg = sb + (sbuf) * STAGE_SZ; \
    _Pragma("unroll") \
    for (int s = 0; s < 4; s++) { \
        uint32_t Ah[2][4], Al[2][4]; \
        _Pragma("unroll") \
        for (int i = 0; i < 2; i++) { \
            const int row = wm * 32 + i * 16 + (lane & 15); \
            const int kb  = s * 32 + ((lane >> 4) << 4); \
            const uint32_t sw = SWZ(row * 128 + kb); \
            LDM_X4(Ah[i], stg + SA_AH + sw); \
            LDM_X4(Al[i], stg + SA_AL + sw); \
        } \
        _Pragma("unroll") \
        for (int g = 0; g < 4; g++) { \
            uint32_t Bh[4]; \
            const int n  = g * 64 + u0w + ((lane >> 4) << 3) + (lane & 7); \
            const int kb = s * 32 + (((lane >> 3) & 1) << 4); \
            const uint32_t sw = SWZ(n * 128 + kb); \
            LDM_X4(Bh, stg + SA_B + sw); \
            _Pragma("unroll") \
            for (int i = 0; i < 2; i++) { \
                MMA_F16(acc[i][g * 2 + 0], Ah[i], Bh[0], Bh[1]); \
                MMA_F16(acc[i][g * 2 + 1], Ah[i], Bh[2], Bh[3]); \
            } \
            _Pragma("unroll") \
            for (int i = 0; i < 2; i++) { \
                MMA_F16(acc[i][g * 2 + 0], Al[i], Bh[0], Bh[1]); \
                MMA_F16(acc[i][g * 2 + 1], Al[i], Bh[2], Bh[3]); \
            } \
        } \
    } }

    for (int t = 0; t < NT; t++) {
        const int hb = t & 1, nb = hb ^ 1;
        const char* A_H = (const char*)g_hbH[hb] + (size_t)brow0 * 1024;
        const char* A_L = (const char*)g_hbL[hb] + (size_t)brow0 * 1024;

        LOAD_CHUNK(0, 0, A_H, A_L);
        CP_COMMIT();

        // accumulator init from packed x_proj (overlaps chunk-0 load)
        {
            const float4* xp = (const float4*)(g_xpP + ((size_t)blockIdx.x * 512 + tid) * 64);
#pragma unroll
            for (int ie = 0; ie < 4; ie++) {
                const int i = ie >> 1, e0 = (ie & 1) * 2;
#pragma unroll
                for (int g = 0; g < 4; g++) {
                    float4 v = __ldg(&xp[ie * 4 + g]);
                    acc[i][g * 2 + 0][e0]     = v.x;
                    acc[i][g * 2 + 0][e0 + 1] = v.y;
                    acc[i][g * 2 + 1][e0]     = v.z;
                    acc[i][g * 2 + 1][e0 + 1] = v.w;
                }
            }
        }

        for (int kc = 0; kc < 8; kc++) {
            if (kc < 7) { LOAD_CHUNK(kc + 1, (kc + 1) & 1, A_H, A_L); CP_COMMIT(); }
            if (kc < 7) CP_WAIT1(); else CP_WAIT0();
            __syncthreads();
            COMPUTE_CHUNK(kc & 1);
            __syncthreads();
        }

        // ---- epilogue: gates -> c,h ; h split to fp16 hi/lo ----
#pragma unroll
        for (int i = 0; i < 2; i++)
#pragma unroll
            for (int eh = 0; eh < 2; eh++) {
                const int b = brow0 + wm * 32 + i * 16 + frow + eh * 8;
                const int U = rank * 64 + u0w + fcol;
#pragma unroll
                for (int u8 = 0; u8 < 2; u8++) {
                    float h2[2];
#pragma unroll
                    for (int p = 0; p < 2; p++) {
                        const int e = eh * 2 + p;
                        float iv = sigx (acc[i][0 + u8][e]);
                        float fv = sigx (acc[i][2 + u8][e]);
                        float gv = tanhx(acc[i][4 + u8][e]);
                        float ov = sigx (acc[i][6 + u8][e]);
                        float cc = fv * cst[i][u8][e] + iv * gv;
                        cst[i][u8][e] = cc;
                        h2[p] = ov * tanhx(cc);
                    }
                    const int Uu = U + u8 * 8;
                    *(float2*)&g_hist[((size_t)t * NB + b) * NH + Uu] =
                        make_float2(h2[0], h2[1]);
                    float l0 = h2[0] - __half2float(__float2half_rn(h2[0]));
                    float l1 = h2[1] - __half2float(__float2half_rn(h2[1]));
                    *(uint32_t*)((char*)g_hbH[nb] + (size_t)b * 1024 + Uu * 2) =
                        pack_h2(h2[0], h2[1]);
                    *(uint32_t*)((char*)g_hbL[nb] + (size_t)b * 1024 + Uu * 2) =
                        pack_h2(l0, l1);
                }
            }

        __threadfence();
        CLUSTER_SYNC();
    }
#undef LOAD_CHUNK
#undef COMPUTE_CHUNK
}

// ---------------------------------------------------------------------------
// Inputs: z, W_ih, W_hh, b_ih, b_hh, W_out, b_out, seq_len
// ---------------------------------------------------------------------------
extern "C" void kernel_launch(void* const* d_in, const int* in_sizes, int n_in,
                              void* d_out, int out_size)
{
    (void)in_sizes; (void)n_in; (void)out_size;
    const float* z    = (const float*)d_in[0];
    const float* Wih  = (const float*)d_in[1];
    const float* Whh  = (const float*)d_in[2];
    const float* bih  = (const float*)d_in[3];
    const float* bhh  = (const float*)d_in[4];
    const float* Wout = (const float*)d_in[5];
    const float* bout = (const float*)d_in[6];
    float* out = (float*)d_out;

    xproj_kernel <<<dim3(N4H / 256, NB / 16), 256>>>(z, Wih, bih, bhh);
    xpack_kernel <<<128, 512>>>();
    whalf_kernel <<<(N4H * NH) / 256, 256>>>(Whh);

    cudaFuncSetAttribute(lstm_mma_kernel, cudaFuncAttributeMaxDynamicSharedMemorySize,
                         SMEM_TOTAL);
    lstm_mma_kernel<<<128, TPB, SMEM_TOTAL>>>();

    outproj_kernel<<<(NT * NB) / 16, 128>>>(Wout, bout, out);
}

// round 13
// speedup vs baseline: 1.7178x; 1.3661x over previous
#include <cuda_runtime.h>
#include <cuda_fp16.h>
#include <cstdint>
#include <math.h>

#define NB   2048
#define NH   512
#define N4H  2048
#define NA   8
#define NZ   64
#define NT   64
#define TPB  512

// 2-stage ring, K=64 per chunk. Stage: A 16K | B 32K = 48KB
#define SA_A  0
#define SA_B  16384
#define STAGE_SZ  49152
#define SMEM_TOTAL (2 * STAGE_SZ)    // 98304

#define SWZ(o) ((o) ^ ((((unsigned)(o)) >> 3) & 0x70))

// ---- device scratch ----
__device__ float  g_xproj[NB * N4H];
__device__ float  g_xpP[(size_t)128 * 512 * 64];   // 64 floats per (cta,tid)
__device__ __half g_Wh[N4H * NH];                  // permuted W_hh, fp16
__device__ __half g_hb[2][NB * NH];                // h (fp16) ping-pong
__device__ float  g_hist[(size_t)NT * NB * NH];

// ================= PTX helpers =================
__device__ __forceinline__ uint32_t smem_u32(const void* p) {
    uint32_t a;
    asm("{ .reg .u64 t; cvta.to.shared.u64 t, %1; cvt.u32.u64 %0, t; }" : "=r"(a) : "l"(p));
    return a;
}
__device__ __forceinline__ void cp16(uint32_t dst, const void* src) {
    asm volatile("cp.async.cg.shared.global [%0], [%1], 16;" :: "r"(dst), "l"(src) : "memory");
}
#define CP_COMMIT() asm volatile("cp.async.commit_group;" ::: "memory")
#define CP_WAIT1()  asm volatile("cp.async.wait_group 1;"  ::: "memory")
#define CP_WAIT0()  asm volatile("cp.async.wait_group 0;"  ::: "memory")
#define CLUSTER_SYNC() do { \
    asm volatile("barrier.cluster.arrive.aligned;" ::: "memory"); \
    asm volatile("barrier.cluster.wait.aligned;"   ::: "memory"); } while (0)

#define LDM_X4(r, ad) \
    asm volatile("ldmatrix.sync.aligned.m8n8.x4.shared.b16 {%0,%1,%2,%3}, [%4];" \
        : "=r"((r)[0]), "=r"((r)[1]), "=r"((r)[2]), "=r"((r)[3]) : "r"(ad))

#define MMA_F16(d, a, b0, b1) \
    asm volatile("mma.sync.aligned.m16n8k16.row.col.f32.f16.f16.f32 " \
        "{%0,%1,%2,%3}, {%4,%5,%6,%7}, {%8,%9}, {%0,%1,%2,%3};" \
        : "+f"((d)[0]), "+f"((d)[1]), "+f"((d)[2]), "+f"((d)[3]) \
        : "r"((a)[0]), "r"((a)[1]), "r"((a)[2]), "r"((a)[3]), "r"(b0), "r"(b1))

__device__ __forceinline__ float sigx(float x)  { return __fdividef(1.0f, 1.0f + __expf(-x)); }
__device__ __forceinline__ float tanhx(float x) { return __fdividef(2.0f, 1.0f + __expf(-2.0f * x)) - 1.0f; }
__device__ __forceinline__ uint32_t pack_h2(float a, float b) {
    __half2 t = __floats2half2_rn(a, b);
    return *(uint32_t*)&t;
}

// ================= prep kernels =================
__global__ __launch_bounds__(256, 1)
void xproj_kernel(const float* __restrict__ z, const float* __restrict__ Wih,
                  const float* __restrict__ bih, const float* __restrict__ bhh)
{
    const int j  = blockIdx.x * 256 + threadIdx.x;
    const int b0 = blockIdx.y * 16;
    __shared__ float zs[16][64];
    for (int i = threadIdx.x; i < 16 * 64; i += 256)
        zs[i >> 6][i & 63] = z[(b0 + (i >> 6)) * NZ + (i & 63)];
    __syncthreads();
    float w[64];
#pragma unroll
    for (int k4 = 0; k4 < 16; k4++) {
        float4 v = *(const float4*)&Wih[j * (NA + NZ) + NA + k4 * 4];
        w[k4*4+0] = v.x; w[k4*4+1] = v.y; w[k4*4+2] = v.z; w[k4*4+3] = v.w;
    }
    const float bias = bih[j] + bhh[j];
#pragma unroll
    for (int bb = 0; bb < 16; bb++) {
        float acc = bias;
#pragma unroll
        for (int k = 0; k < 64; k++) acc += zs[bb][k] * w[k];
        g_xproj[(size_t)(b0 + bb) * N4H + j] = acc;
    }
}

// pack x_proj per (cta,tid) in accumulator-init order + zero h buffer 0
__global__ __launch_bounds__(512, 1)
void xpack_kernel()
{
    const int cta = blockIdx.x, tid = threadIdx.x;
    const int rank = cta & 7, brow0 = (cta >> 3) * 128;
    const int lane = tid & 31, wid = tid >> 5;
    const int wm = wid & 3, u0w = (wid >> 2) * 16;
    const int frow = lane >> 2, fcol = (lane & 3) * 2;
    float* dst = g_xpP + ((size_t)cta * 512 + tid) * 64;
    int idx = 0;
#pragma unroll
    for (int i = 0; i < 2; i++)
#pragma unroll
        for (int eh = 0; eh < 2; eh++) {
            const int b = brow0 + wm * 32 + i * 16 + frow + eh * 8;
#pragma unroll
            for (int g = 0; g < 4; g++)
#pragma unroll
                for (int u8 = 0; u8 < 2; u8++) {
                    const int col = g * 512 + rank * 64 + u0w + u8 * 8 + fcol;
                    dst[idx++] = g_xproj[(size_t)b * N4H + col];
                    dst[idx++] = g_xproj[(size_t)b * N4H + col + 1];
                }
        }
    // zero h ping-pong buffer 0: 512K u32, 65536 threads -> 8 each
    const int gt = cta * 512 + tid;
#pragma unroll
    for (int r = 0; r < 8; r++)
        ((uint32_t*)&g_hb[0][0])[gt + r * 65536] = 0;
}

// W -> fp16 with row permutation: p = rank*256 + gate*64 + jj
__global__ __launch_bounds__(256, 1)
void whalf_kernel(const float* __restrict__ Whh)
{
    const int g = blockIdx.x * 256 + threadIdx.x;
    const int p = g >> 9, k = g & 511;
    const int orow = ((p >> 6) & 3) * 512 + (p >> 8) * 64 + (p & 63);
    g_Wh[g] = __float2half_rn(Whh[(size_t)orow * NH + k]);
}

__global__ __launch_bounds__(128, 1)
void outproj_kernel(const float* __restrict__ Wout, const float* __restrict__ bout,
                    float* __restrict__ out)
{
    __shared__ float hs[16][516];
    const int tid = threadIdx.x;
    const size_t r0 = (size_t)blockIdx.x * 16;
    const float4* src = (const float4*)&g_hist[r0 * NH];
    for (int i = tid; i < 16 * 128; i += 128) {
        float4 v = src[i];
        *(float4*)&hs[i >> 7][(i & 127) * 4] = v;
    }
    __syncthreads();
    const int r = tid >> 3, a = tid & 7;
    float s = bout[a];
    const float* hp = hs[r];
#pragma unroll 4
    for (int u4 = 0; u4 < 128; u4++) {
        float4 wq = __ldg((const float4*)&Wout[a * NH + u4 * 4]);
        float4 hq = *(const float4*)&hp[u4 * 4];
        s += hq.x * wq.x + hq.y * wq.y + hq.z * wq.z + hq.w * wq.w;
    }
    const size_t row = r0 + r;
    const int t = (int)(row >> 11), b = (int)(row & 2047);
    out[((size_t)b * NT + t) * NA + a] = s;
}

// ================= main LSTM kernel (fp16 single-pass) =================
extern __shared__ char dsm[];

__global__ __launch_bounds__(TPB, 1) __cluster_dims__(8, 1, 1)
void lstm_mma_kernel()
{
    const uint32_t sb = smem_u32(dsm);
    const int tid  = threadIdx.x;
    const int lane = tid & 31;
    const int wid  = tid >> 5;
    const int wm   = wid & 3;          // M block of 32 rows
    const int u0w  = (wid >> 2) * 16;  // u block of 16
    const int rank  = blockIdx.x & 7;
    const int brow0 = (blockIdx.x >> 3) * 128;
    const int frow = lane >> 2;
    const int fcol = (lane & 3) * 2;

    float acc[2][8][4];
    float cst[2][2][4];
#pragma unroll
    for (int i = 0; i < 2; i++)
#pragma unroll
        for (int u8 = 0; u8 < 2; u8++)
#pragma unroll
            for (int e = 0; e < 4; e++) cst[i][u8][e] = 0.0f;

    const char* Wbase = (const char*)g_Wh + (size_t)rank * 256 * 1024;

// A: 16KB -> 2 cp16/thread; B: 32KB -> 4/thread (512 thr)
#define LOAD_CHUNK(kc, sbuf, Ap) { \
    const uint32_t stg = sb + (sbuf) * STAGE_SZ; \
    _Pragma("unroll") \
    for (int ii = 0; ii < 2; ii++) { \
        int q = tid + ii * 512, row = q >> 3, c16 = (q & 7) * 16; \
        uint32_t sw = SWZ(row * 128 + c16); \
        size_t so = (size_t)row * 1024 + (size_t)(kc) * 128 + c16; \
        cp16(stg + SA_A + sw, (Ap) + so); \
    } \
    _Pragma("unroll") \
    for (int ii = 0; ii < 4; ii++) { \
        int q = tid + ii * 512, row = q >> 3, c16 = (q & 7) * 16; \
        uint32_t sw = SWZ(row * 128 + c16); \
        size_t so = (size_t)row * 1024 + (size_t)(kc) * 128 + c16; \
        cp16(stg + SA_B + sw, Wbase + so); \
    } }

#define COMPUTE_CHUNK(sbuf) { \
    const uint32_t stg = sb + (sbuf) * STAGE_SZ; \
    _Pragma("unroll") \
    for (int s = 0; s < 4; s++) { \
        uint32_t Ah[2][4]; \
        _Pragma("unroll") \
        for (int i = 0; i < 2; i++) { \
            const int row = wm * 32 + i * 16 + (lane & 15); \
            const int kb  = s * 32 + ((lane >> 4) << 4); \
            const uint32_t sw = SWZ(row * 128 + kb); \
            LDM_X4(Ah[i], stg + SA_A + sw); \
        } \
        _Pragma("unroll") \
        for (int g = 0; g < 4; g++) { \
            uint32_t Bh[4]; \
            const int n  = g * 64 + u0w + ((lane >> 4) << 3) + (lane & 7); \
            const int kb = s * 32 + (((lane >> 3) & 1) << 4); \
            const uint32_t sw = SWZ(n * 128 + kb); \
            LDM_X4(Bh, stg + SA_B + sw); \
            _Pragma("unroll") \
            for (int i = 0; i < 2; i++) { \
                MMA_F16(acc[i][g * 2 + 0], Ah[i], Bh[0], Bh[1]); \
                MMA_F16(acc[i][g * 2 + 1], Ah[i], Bh[2], Bh[3]); \
            } \
        } \
    } }

    for (int t = 0; t < NT; t++) {
        const int hb = t & 1, nb = hb ^ 1;
        const char* A_P = (const char*)g_hb[hb] + (size_t)brow0 * 1024;

        LOAD_CHUNK(0, 0, A_P);
        CP_COMMIT();

        // accumulator init from packed x_proj (overlaps chunk-0 load)
        {
            const float4* xp = (const float4*)(g_xpP + ((size_t)blockIdx.x * 512 + tid) * 64);
#pragma unroll
            for (int ie = 0; ie < 4; ie++) {
                const int i = ie >> 1, e0 = (ie & 1) * 2;
#pragma unroll
                for (int g = 0; g < 4; g++) {
                    float4 v = __ldg(&xp[ie * 4 + g]);
                    acc[i][g * 2 + 0][e0]     = v.x;
                    acc[i][g * 2 + 0][e0 + 1] = v.y;
                    acc[i][g * 2 + 1][e0]     = v.z;
                    acc[i][g * 2 + 1][e0 + 1] = v.w;
                }
            }
        }

        for (int kc = 0; kc < 8; kc++) {
            if (kc < 7) { LOAD_CHUNK(kc + 1, (kc + 1) & 1, A_P); CP_COMMIT(); }
            if (kc < 7) CP_WAIT1(); else CP_WAIT0();
            __syncthreads();
            COMPUTE_CHUNK(kc & 1);
            __syncthreads();
        }

        // ---- epilogue: gates -> c,h ; h stored fp16 ----
#pragma unroll
        for (int i = 0; i < 2; i++)
#pragma unroll
            for (int eh = 0; eh < 2; eh++) {
                const int b = brow0 + wm * 32 + i * 16 + frow + eh * 8;
                const int U = rank * 64 + u0w + fcol;
#pragma unroll
                for (int u8 = 0; u8 < 2; u8++) {
                    float h2[2];
#pragma unroll
                    for (int p = 0; p < 2; p++) {
                        const int e = eh * 2 + p;
                        float iv = sigx (acc[i][0 + u8][e]);
                        float fv = sigx (acc[i][2 + u8][e]);
                        float gv = tanhx(acc[i][4 + u8][e]);
                        float ov = sigx (acc[i][6 + u8][e]);
                        float cc = fv * cst[i][u8][e] + iv * gv;
                        cst[i][u8][e] = cc;
                        h2[p] = ov * tanhx(cc);
                    }
                    const int Uu = U + u8 * 8;
                    *(float2*)&g_hist[((size_t)t * NB + b) * NH + Uu] =
                        make_float2(h2[0], h2[1]);
                    *(uint32_t*)((char*)g_hb[nb] + (size_t)b * 1024 + Uu * 2) =
                        pack_h2(h2[0], h2[1]);
                }
            }

        __threadfence();
        CLUSTER_SYNC();
    }
#undef LOAD_CHUNK
#undef COMPUTE_CHUNK
}

// ---------------------------------------------------------------------------
// Inputs: z, W_ih, W_hh, b_ih, b_hh, W_out, b_out, seq_len
// ---------------------------------------------------------------------------
extern "C" void kernel_launch(void* const* d_in, const int* in_sizes, int n_in,
                              void* d_out, int out_size)
{
    (void)in_sizes; (void)n_in; (void)out_size;
    const float* z    = (const float*)d_in[0];
    const float* Wih  = (const float*)d_in[1];
    const float* Whh  = (const float*)d_in[2];
    const float* bih  = (const float*)d_in[3];
    const float* bhh  = (const float*)d_in[4];
    const float* Wout = (const float*)d_in[5];
    const float* bout = (const float*)d_in[6];
    float* out = (float*)d_out;

    xproj_kernel <<<dim3(N4H / 256, NB / 16), 256>>>(z, Wih, bih, bhh);
    xpack_kernel <<<128, 512>>>();
    whalf_kernel <<<(N4H * NH) / 256, 256>>>(Whh);

    cudaFuncSetAttribute(lstm_mma_kernel, cudaFuncAttributeMaxDynamicSharedMemorySize,
                         SMEM_TOTAL);
    lstm_mma_kernel<<<128, TPB, SMEM_TOTAL>>>();

    outproj_kernel<<<(NT * NB) / 16, 128>>>(Wout, bout, out);
}

// round 14
// speedup vs baseline: 2.8072x; 1.6342x over previous
#include <cuda_runtime.h>
#include <cuda_fp16.h>
#include <cstdint>
#include <math.h>

#define NB   2048
#define NH   512
#define N4H  2048
#define NA   8
#define NZ   64
#define NT   64
#define TPB  256

// 2-stage ring, K=64 per chunk. Stage: A 8K | B 32K = 40KB (M=64 per CTA)
#define SA_A  0
#define SA_B  8192
#define STAGE_SZ  40960
#define SMEM_TOTAL (2 * STAGE_SZ)    // 81920 -> 2 CTAs/SM = 160KB

#define SWZ(o) ((o) ^ ((((unsigned)(o)) >> 3) & 0x70))

// ---- device scratch ----
__device__ float  g_xproj[NB * N4H];
__device__ float  g_xpP[(size_t)256 * 256 * 64];   // 64 floats per (cta,tid)
__device__ __half g_Wh[N4H * NH];                  // permuted W_hh, fp16
__device__ __half g_hb[2][NB * NH];                // h (fp16) ping-pong
__device__ float  g_hist[(size_t)NT * NB * NH];

// ================= PTX helpers =================
__device__ __forceinline__ uint32_t smem_u32(const void* p) {
    uint32_t a;
    asm("{ .reg .u64 t; cvta.to.shared.u64 t, %1; cvt.u32.u64 %0, t; }" : "=r"(a) : "l"(p));
    return a;
}
__device__ __forceinline__ void cp16(uint32_t dst, const void* src) {
    asm volatile("cp.async.cg.shared.global [%0], [%1], 16;" :: "r"(dst), "l"(src) : "memory");
}
#define CP_COMMIT() asm volatile("cp.async.commit_group;" ::: "memory")
#define CP_WAIT1()  asm volatile("cp.async.wait_group 1;"  ::: "memory")
#define CP_WAIT0()  asm volatile("cp.async.wait_group 0;"  ::: "memory")
#define CLUSTER_SYNC() do { \
    asm volatile("barrier.cluster.arrive.aligned;" ::: "memory"); \
    asm volatile("barrier.cluster.wait.aligned;"   ::: "memory"); } while (0)

#define LDM_X4(r, ad) \
    asm volatile("ldmatrix.sync.aligned.m8n8.x4.shared.b16 {%0,%1,%2,%3}, [%4];" \
        : "=r"((r)[0]), "=r"((r)[1]), "=r"((r)[2]), "=r"((r)[3]) : "r"(ad))

#define MMA_F16(d, a, b0, b1) \
    asm volatile("mma.sync.aligned.m16n8k16.row.col.f32.f16.f16.f32 " \
        "{%0,%1,%2,%3}, {%4,%5,%6,%7}, {%8,%9}, {%0,%1,%2,%3};" \
        : "+f"((d)[0]), "+f"((d)[1]), "+f"((d)[2]), "+f"((d)[3]) \
        : "r"((a)[0]), "r"((a)[1]), "r"((a)[2]), "r"((a)[3]), "r"(b0), "r"(b1))

__device__ __forceinline__ float sigx(float x)  { return __fdividef(1.0f, 1.0f + __expf(-x)); }
__device__ __forceinline__ float tanhx(float x) { return __fdividef(2.0f, 1.0f + __expf(-2.0f * x)) - 1.0f; }
__device__ __forceinline__ uint32_t pack_h2(float a, float b) {
    __half2 t = __floats2half2_rn(a, b);
    return *(uint32_t*)&t;
}

// ================= prep kernels =================
__global__ __launch_bounds__(256, 1)
void xproj_kernel(const float* __restrict__ z, const float* __restrict__ Wih,
                  const float* __restrict__ bih, const float* __restrict__ bhh)
{
    const int j  = blockIdx.x * 256 + threadIdx.x;
    const int b0 = blockIdx.y * 16;
    __shared__ float zs[16][64];
    for (int i = threadIdx.x; i < 16 * 64; i += 256)
        zs[i >> 6][i & 63] = z[(b0 + (i >> 6)) * NZ + (i & 63)];
    __syncthreads();
    float w[64];
#pragma unroll
    for (int k4 = 0; k4 < 16; k4++) {
        float4 v = *(const float4*)&Wih[j * (NA + NZ) + NA + k4 * 4];
        w[k4*4+0] = v.x; w[k4*4+1] = v.y; w[k4*4+2] = v.z; w[k4*4+3] = v.w;
    }
    const float bias = bih[j] + bhh[j];
#pragma unroll
    for (int bb = 0; bb < 16; bb++) {
        float acc = bias;
#pragma unroll
        for (int k = 0; k < 64; k++) acc += zs[bb][k] * w[k];
        g_xproj[(size_t)(b0 + bb) * N4H + j] = acc;
    }
}

// pack x_proj per (cta,tid) in accumulator-init order + zero h buffer 0
// Layout for grid=256, TPB=256: cta -> rank=cta&7, group=(cta>>3), brow0=group*64
__global__ __launch_bounds__(256, 1)
void xpack_kernel()
{
    const int cta = blockIdx.x, tid = threadIdx.x;
    const int rank = cta & 7, brow0 = (cta >> 3) * 64;
    const int lane = tid & 31, wid = tid >> 5;
    const int wm = wid & 1, u0w = (wid >> 1) * 16;
    const int frow = lane >> 2, fcol = (lane & 3) * 2;
    float* dst = g_xpP + ((size_t)cta * 256 + tid) * 64;
    int idx = 0;
#pragma unroll
    for (int i = 0; i < 2; i++)
#pragma unroll
        for (int eh = 0; eh < 2; eh++) {
            const int b = brow0 + wm * 32 + i * 16 + frow + eh * 8;
#pragma unroll
            for (int g = 0; g < 4; g++)
#pragma unroll
                for (int u8 = 0; u8 < 2; u8++) {
                    const int col = g * 512 + rank * 64 + u0w + u8 * 8 + fcol;
                    dst[idx++] = g_xproj[(size_t)b * N4H + col];
                    dst[idx++] = g_xproj[(size_t)b * N4H + col + 1];
                }
        }
    // zero h ping-pong buffer 0: 512K u32, 65536 threads -> 8 each
    const int gt = cta * 256 + tid;
#pragma unroll
    for (int r = 0; r < 8; r++)
        ((uint32_t*)&g_hb[0][0])[gt + r * 65536] = 0;
}

// W -> fp16 with row permutation: p = rank*256 + gate*64 + jj
__global__ __launch_bounds__(256, 1)
void whalf_kernel(const float* __restrict__ Whh)
{
    const int g = blockIdx.x * 256 + threadIdx.x;
    const int p = g >> 9, k = g & 511;
    const int orow = ((p >> 6) & 3) * 512 + (p >> 8) * 64 + (p & 63);
    g_Wh[g] = __float2half_rn(Whh[(size_t)orow * NH + k]);
}

__global__ __launch_bounds__(128, 1)
void outproj_kernel(const float* __restrict__ Wout, const float* __restrict__ bout,
                    float* __restrict__ out)
{
    __shared__ float hs[16][516];
    const int tid = threadIdx.x;
    const size_t r0 = (size_t)blockIdx.x * 16;
    const float4* src = (const float4*)&g_hist[r0 * NH];
    for (int i = tid; i < 16 * 128; i += 128) {
        float4 v = src[i];
        *(float4*)&hs[i >> 7][(i & 127) * 4] = v;
    }
    __syncthreads();
    const int r = tid >> 3, a = tid & 7;
    float s = bout[a];
    const float* hp = hs[r];
#pragma unroll 4
    for (int u4 = 0; u4 < 128; u4++) {
        float4 wq = __ldg((const float4*)&Wout[a * NH + u4 * 4]);
        float4 hq = *(const float4*)&hp[u4 * 4];
        s += hq.x * wq.x + hq.y * wq.y + hq.z * wq.z + hq.w * wq.w;
    }
    const size_t row = r0 + r;
    const int t = (int)(row >> 11), b = (int)(row & 2047);
    out[((size_t)b * NT + t) * NA + a] = s;
}

// ================= main LSTM kernel (fp16 single-pass, 2 CTAs/SM) =================
extern __shared__ char dsm[];

__global__ __launch_bounds__(TPB, 2) __cluster_dims__(8, 1, 1)
void lstm_mma_kernel()
{
    const uint32_t sb = smem_u32(dsm);
    const int tid  = threadIdx.x;
    const int lane = tid & 31;
    const int wid  = tid >> 5;
    const int wm   = wid & 1;          // M block of 32 rows (M=64 per CTA)
    const int u0w  = (wid >> 1) * 16;  // u block of 16
    const int rank  = blockIdx.x & 7;
    const int brow0 = (blockIdx.x >> 3) * 64;
    const int frow = lane >> 2;
    const int fcol = (lane & 3) * 2;

    float acc[2][8][4];
    float cst[2][2][4];
#pragma unroll
    for (int i = 0; i < 2; i++)
#pragma unroll
        for (int u8 = 0; u8 < 2; u8++)
#pragma unroll
            for (int e = 0; e < 4; e++) cst[i][u8][e] = 0.0f;

    const char* Wbase = (const char*)g_Wh + (size_t)rank * 256 * 1024;

// A: 8KB -> 512 x 16B / 256 thr = 2 each; B: 32KB -> 2048 -> 8 each
#define LOAD_CHUNK(kc, sbuf, Ap) { \
    const uint32_t stg = sb + (sbuf) * STAGE_SZ; \
    _Pragma("unroll") \
    for (int ii = 0; ii < 2; ii++) { \
        int q = tid + ii * 256, row = q >> 3, c16 = (q & 7) * 16; \
        uint32_t sw = SWZ(row * 128 + c16); \
        size_t so = (size_t)row * 1024 + (size_t)(kc) * 128 + c16; \
        cp16(stg + SA_A + sw, (Ap) + so); \
    } \
    _Pragma("unroll") \
    for (int ii = 0; ii < 8; ii++) { \
        int q = tid + ii * 256, row = q >> 3, c16 = (q & 7) * 16; \
        uint32_t sw = SWZ(row * 128 + c16); \
        size_t so = (size_t)row * 1024 + (size_t)(kc) * 128 + c16; \
        cp16(stg + SA_B + sw, Wbase + so); \
    } }

#define COMPUTE_CHUNK(sbuf) { \
    const uint32_t stg = sb + (sbuf) * STAGE_SZ; \
    _Pragma("unroll") \
    for (int s = 0; s < 4; s++) { \
        uint32_t Ah[2][4]; \
        _Pragma("unroll") \
        for (int i = 0; i < 2; i++) { \
            const int row = wm * 32 + i * 16 + (lane & 15); \
            const int kb  = s * 32 + ((lane >> 4) << 4); \
            const uint32_t sw = SWZ(row * 128 + kb); \
            LDM_X4(Ah[i], stg + SA_A + sw); \
        } \
        _Pragma("unroll") \
        for (int g = 0; g < 4; g++) { \
            uint32_t Bh[4]; \
            const int n  = g * 64 + u0w + ((lane >> 4) << 3) + (lane & 7); \
            const int kb = s * 32 + (((lane >> 3) & 1) << 4); \
            const uint32_t sw = SWZ(n * 128 + kb); \
            LDM_X4(Bh, stg + SA_B + sw); \
            _Pragma("unroll") \
            for (int i = 0; i < 2; i++) { \
                MMA_F16(acc[i][g * 2 + 0], Ah[i], Bh[0], Bh[1]); \
                MMA_F16(acc[i][g * 2 + 1], Ah[i], Bh[2], Bh[3]); \
            } \
        } \
    } }

    for (int t = 0; t < NT; t++) {
        const int hb = t & 1, nb = hb ^ 1;
        const char* A_P = (const char*)g_hb[hb] + (size_t)brow0 * 1024;

        LOAD_CHUNK(0, 0, A_P);
        CP_COMMIT();

        // accumulator init from packed x_proj (overlaps chunk-0 load)
        {
            const float4* xp = (const float4*)(g_xpP + ((size_t)blockIdx.x * 256 + tid) * 64);
#pragma unroll
            for (int ie = 0; ie < 4; ie++) {
                const int i = ie >> 1, e0 = (ie & 1) * 2;
#pragma unroll
                for (int g = 0; g < 4; g++) {
                    float4 v = __ldg(&xp[ie * 4 + g]);
                    acc[i][g * 2 + 0][e0]     = v.x;
                    acc[i][g * 2 + 0][e0 + 1] = v.y;
                    acc[i][g * 2 + 1][e0]     = v.z;
                    acc[i][g * 2 + 1][e0 + 1] = v.w;
                }
            }
        }

        for (int kc = 0; kc < 8; kc++) {
            if (kc < 7) { LOAD_CHUNK(kc + 1, (kc + 1) & 1, A_P); CP_COMMIT(); }
            if (kc < 7) CP_WAIT1(); else CP_WAIT0();
            __syncthreads();
            COMPUTE_CHUNK(kc & 1);
            __syncthreads();
        }

        // ---- epilogue: gates -> c,h ; h stored fp16 ----
#pragma unroll
        for (int i = 0; i < 2; i++)
#pragma unroll
            for (int eh = 0; eh < 2; eh++) {
                const int b = brow0 + wm * 32 + i * 16 + frow + eh * 8;
                const int U = rank * 64 + u0w + fcol;
#pragma unroll
                for (int u8 = 0; u8 < 2; u8++) {
                    float h2[2];
#pragma unroll
                    for (int p = 0; p < 2; p++) {
                        const int e = eh * 2 + p;
                        float iv = sigx (acc[i][0 + u8][e]);
                        float fv = sigx (acc[i][2 + u8][e]);
                        float gv = tanhx(acc[i][4 + u8][e]);
                        float ov = sigx (acc[i][6 + u8][e]);
                        float cc = fv * cst[i][u8][e] + iv * gv;
                        cst[i][u8][e] = cc;
                        h2[p] = ov * tanhx(cc);
                    }
                    const int Uu = U + u8 * 8;
                    *(float2*)&g_hist[((size_t)t * NB + b) * NH + Uu] =
                        make_float2(h2[0], h2[1]);
                    *(uint32_t*)((char*)g_hb[nb] + (size_t)b * 1024 + Uu * 2) =
                        pack_h2(h2[0], h2[1]);
                }
            }

        __threadfence();
        CLUSTER_SYNC();
    }
#undef LOAD_CHUNK
#undef COMPUTE_CHUNK
}

// ---------------------------------------------------------------------------
// Inputs: z, W_ih, W_hh, b_ih, b_hh, W_out, b_out, seq_len
// ---------------------------------------------------------------------------
extern "C" void kernel_launch(void* const* d_in, const int* in_sizes, int n_in,
                              void* d_out, int out_size)
{
    (void)in_sizes; (void)n_in; (void)out_size;
    const float* z    = (const float*)d_in[0];
    const float* Wih  = (const float*)d_in[1];
    const float* Whh  = (const float*)d_in[2];
    const float* bih  = (const float*)d_in[3];
    const float* bhh  = (const float*)d_in[4];
    const float* Wout = (const float*)d_in[5];
    const float* bout = (const float*)d_in[6];
    float* out = (float*)d_out;

    xproj_kernel <<<dim3(N4H / 256, NB / 16), 256>>>(z, Wih, bih, bhh);
    xpack_kernel <<<256, 256>>>();
    whalf_kernel <<<(N4H * NH) / 256, 256>>>(Whh);

    cudaFuncSetAttribute(lstm_mma_kernel, cudaFuncAttributeMaxDynamicSharedMemorySize,
                         SMEM_TOTAL);
    lstm_mma_kernel<<<256, TPB, SMEM_TOTAL>>>();

    outproj_kernel<<<(NT * NB) / 16, 128>>>(Wout, bout, out);
}

// round 15
// speedup vs baseline: 2.9407x; 1.0476x over previous
#include <cuda_runtime.h>
#include <cuda_fp16.h>
#include <cstdint>
#include <math.h>

#define NB   2048
#define NH   512
#define N4H  2048
#define NA   8
#define NZ   64
#define NT   64
#define TPB  256

// 2-stage ring, K=64 per chunk. Stage: A 8K | B 32K = 40KB (M=64 per CTA)
#define SA_A  0
#define SA_B  8192
#define STAGE_SZ  40960
#define SMEM_TOTAL (2 * STAGE_SZ)    // 81920 -> 2 CTAs/SM = 160KB

#define SWZ(o) ((o) ^ ((((unsigned)(o)) >> 3) & 0x70))

// ---- device scratch ----
__device__ float  g_xproj[NB * N4H];
__device__ float  g_xpP[(size_t)256 * 256 * 64];   // 64 floats per (cta,tid)
__device__ __half g_Wh[N4H * NH];                  // permuted W_hh, fp16
__device__ __half g_hb[2][NB * NH];                // h (fp16) ping-pong
__device__ float  g_hist[(size_t)NT * NB * NH];

// ================= PTX helpers =================
__device__ __forceinline__ uint32_t smem_u32(const void* p) {
    uint32_t a;
    asm("{ .reg .u64 t; cvta.to.shared.u64 t, %1; cvt.u32.u64 %0, t; }" : "=r"(a) : "l"(p));
    return a;
}
__device__ __forceinline__ void cp16(uint32_t dst, const void* src) {
    asm volatile("cp.async.cg.shared.global [%0], [%1], 16;" :: "r"(dst), "l"(src) : "memory");
}
#define CP_COMMIT() asm volatile("cp.async.commit_group;" ::: "memory")
#define CP_WAIT1()  asm volatile("cp.async.wait_group 1;"  ::: "memory")
#define CP_WAIT0()  asm volatile("cp.async.wait_group 0;"  ::: "memory")
#define CLUSTER_SYNC() do { \
    asm volatile("barrier.cluster.arrive.aligned;" ::: "memory"); \
    asm volatile("barrier.cluster.wait.aligned;"   ::: "memory"); } while (0)

#define LDM_X4(r, ad) \
    asm volatile("ldmatrix.sync.aligned.m8n8.x4.shared.b16 {%0,%1,%2,%3}, [%4];" \
        : "=r"((r)[0]), "=r"((r)[1]), "=r"((r)[2]), "=r"((r)[3]) : "r"(ad))

#define MMA_F16(d, a, b0, b1) \
    asm volatile("mma.sync.aligned.m16n8k16.row.col.f32.f16.f16.f32 " \
        "{%0,%1,%2,%3}, {%4,%5,%6,%7}, {%8,%9}, {%0,%1,%2,%3};" \
        : "+f"((d)[0]), "+f"((d)[1]), "+f"((d)[2]), "+f"((d)[3]) \
        : "r"((a)[0]), "r"((a)[1]), "r"((a)[2]), "r"((a)[3]), "r"(b0), "r"(b1))

__device__ __forceinline__ float tanhA(float x) {
    float y; asm("tanh.approx.f32 %0, %1;" : "=f"(y) : "f"(x)); return y;
}
__device__ __forceinline__ float sigA(float x) {
    return fmaf(tanhA(0.5f * x), 0.5f, 0.5f);
}
__device__ __forceinline__ float sigx(float x)  { return __fdividef(1.0f, 1.0f + __expf(-x)); }
__device__ __forceinline__ uint32_t pack_h2(float a, float b) {
    __half2 t = __floats2half2_rn(a, b);
    return *(uint32_t*)&t;
}

// ================= prep kernels =================
__global__ __launch_bounds__(256, 1)
void xproj_kernel(const float* __restrict__ z, const float* __restrict__ Wih,
                  const float* __restrict__ bih, const float* __restrict__ bhh)
{
    const int j  = blockIdx.x * 256 + threadIdx.x;
    const int b0 = blockIdx.y * 16;
    __shared__ float zs[16][64];
    for (int i = threadIdx.x; i < 16 * 64; i += 256)
        zs[i >> 6][i & 63] = z[(b0 + (i >> 6)) * NZ + (i & 63)];
    __syncthreads();
    float w[64];
#pragma unroll
    for (int k4 = 0; k4 < 16; k4++) {
        float4 v = *(const float4*)&Wih[j * (NA + NZ) + NA + k4 * 4];
        w[k4*4+0] = v.x; w[k4*4+1] = v.y; w[k4*4+2] = v.z; w[k4*4+3] = v.w;
    }
    const float bias = bih[j] + bhh[j];
#pragma unroll
    for (int bb = 0; bb < 16; bb++) {
        float acc = bias;
#pragma unroll
        for (int k = 0; k < 64; k++) acc += zs[bb][k] * w[k];
        g_xproj[(size_t)(b0 + bb) * N4H + j] = acc;
    }
}

// pack x_proj per (cta,tid) in accumulator-init order + zero h buffer 0
__global__ __launch_bounds__(256, 1)
void xpack_kernel()
{
    const int cta = blockIdx.x, tid = threadIdx.x;
    const int rank = cta & 7, brow0 = (cta >> 3) * 64;
    const int lane = tid & 31, wid = tid >> 5;
    const int wm = wid & 1, u0w = (wid >> 1) * 16;
    const int frow = lane >> 2, fcol = (lane & 3) * 2;
    float* dst = g_xpP + ((size_t)cta * 256 + tid) * 64;
    int idx = 0;
#pragma unroll
    for (int i = 0; i < 2; i++)
#pragma unroll
        for (int eh = 0; eh < 2; eh++) {
            const int b = brow0 + wm * 32 + i * 16 + frow + eh * 8;
#pragma unroll
            for (int g = 0; g < 4; g++)
#pragma unroll
                for (int u8 = 0; u8 < 2; u8++) {
                    const int col = g * 512 + rank * 64 + u0w + u8 * 8 + fcol;
                    dst[idx++] = g_xproj[(size_t)b * N4H + col];
                    dst[idx++] = g_xproj[(size_t)b * N4H + col + 1];
                }
        }
    const int gt = cta * 256 + tid;
#pragma unroll
    for (int r = 0; r < 8; r++)
        ((uint32_t*)&g_hb[0][0])[gt + r * 65536] = 0;
}

// W -> fp16 with row permutation: p = rank*256 + gate*64 + jj
__global__ __launch_bounds__(256, 1)
void whalf_kernel(const float* __restrict__ Whh)
{
    const int g = blockIdx.x * 256 + threadIdx.x;
    const int p = g >> 9, k = g & 511;
    const int orow = ((p >> 6) & 3) * 512 + (p >> 8) * 64 + (p & 63);
    g_Wh[g] = __float2half_rn(Whh[(size_t)orow * NH + k]);
}

__global__ __launch_bounds__(128, 1)
void outproj_kernel(const float* __restrict__ Wout, const float* __restrict__ bout,
                    float* __restrict__ out)
{
    __shared__ float hs[16][516];
    const int tid = threadIdx.x;
    const size_t r0 = (size_t)blockIdx.x * 16;
    const float4* src = (const float4*)&g_hist[r0 * NH];
    for (int i = tid; i < 16 * 128; i += 128) {
        float4 v = src[i];
        *(float4*)&hs[i >> 7][(i & 127) * 4] = v;
    }
    __syncthreads();
    const int r = tid >> 3, a = tid & 7;
    float s = bout[a];
    const float* hp = hs[r];
#pragma unroll 4
    for (int u4 = 0; u4 < 128; u4++) {
        float4 wq = __ldg((const float4*)&Wout[a * NH + u4 * 4]);
        float4 hq = *(const float4*)&hp[u4 * 4];
        s += hq.x * wq.x + hq.y * wq.y + hq.z * wq.z + hq.w * wq.w;
    }
    const size_t row = r0 + r;
    const int t = (int)(row >> 11), b = (int)(row & 2047);
    out[((size_t)b * NT + t) * NA + a] = s;
}

// ================= main LSTM kernel (fp16, tanh.approx, B-prefetch) =================
extern __shared__ char dsm[];

__global__ __launch_bounds__(TPB, 2) __cluster_dims__(8, 1, 1)
void lstm_mma_kernel()
{
    const uint32_t sb = smem_u32(dsm);
    const int tid  = threadIdx.x;
    const int lane = tid & 31;
    const int wid  = tid >> 5;
    const int wm   = wid & 1;          // M block of 32 rows (M=64 per CTA)
    const int u0w  = (wid >> 1) * 16;  // u block of 16
    const int rank  = blockIdx.x & 7;
    const int brow0 = (blockIdx.x >> 3) * 64;
    const int frow = lane >> 2;
    const int fcol = (lane & 3) * 2;

    float acc[2][8][4];
    float cst[2][2][4];
#pragma unroll
    for (int i = 0; i < 2; i++)
#pragma unroll
        for (int u8 = 0; u8 < 2; u8++)
#pragma unroll
            for (int e = 0; e < 4; e++) cst[i][u8][e] = 0.0f;

    const char* Wbase = (const char*)g_Wh + (size_t)rank * 256 * 1024;

// A part: 8KB -> 2 cp16/thread; B part: 32KB -> 8 cp16/thread (256 thr)
#define LOAD_A_PART(kc, sbuf, Ap) { \
    const uint32_t stg = sb + (sbuf) * STAGE_SZ; \
    _Pragma("unroll") \
    for (int ii = 0; ii < 2; ii++) { \
        int q = tid + ii * 256, row = q >> 3, c16 = (q & 7) * 16; \
        uint32_t sw = SWZ(row * 128 + c16); \
        size_t so = (size_t)row * 1024 + (size_t)(kc) * 128 + c16; \
        cp16(stg + SA_A + sw, (Ap) + so); \
    } }

#define LOAD_B_PART(kc, sbuf) { \
    const uint32_t stg = sb + (sbuf) * STAGE_SZ; \
    _Pragma("unroll") \
    for (int ii = 0; ii < 8; ii++) { \
        int q = tid + ii * 256, row = q >> 3, c16 = (q & 7) * 16; \
        uint32_t sw = SWZ(row * 128 + c16); \
        size_t so = (size_t)row * 1024 + (size_t)(kc) * 128 + c16; \
        cp16(stg + SA_B + sw, Wbase + so); \
    } }

#define COMPUTE_CHUNK(sbuf) { \
    const uint32_t stg = sb + (sbuf) * STAGE_SZ; \
    _Pragma("unroll") \
    for (int s = 0; s < 4; s++) { \
        uint32_t Ah[2][4]; \
        _Pragma("unroll") \
        for (int i = 0; i < 2; i++) { \
            const int row = wm * 32 + i * 16 + (lane & 15); \
            const int kb  = s * 32 + ((lane >> 4) << 4); \
            const uint32_t sw = SWZ(row * 128 + kb); \
            LDM_X4(Ah[i], stg + SA_A + sw); \
        } \
        _Pragma("unroll") \
        for (int g = 0; g < 4; g++) { \
            uint32_t Bh[4]; \
            const int n  = g * 64 + u0w + ((lane >> 4) << 3) + (lane & 7); \
            const int kb = s * 32 + (((lane >> 3) & 1) << 4); \
            const uint32_t sw = SWZ(n * 128 + kb); \
            LDM_X4(Bh, stg + SA_B + sw); \
            _Pragma("unroll") \
            for (int i = 0; i < 2; i++) { \
                MMA_F16(acc[i][g * 2 + 0], Ah[i], Bh[0], Bh[1]); \
                MMA_F16(acc[i][g * 2 + 1], Ah[i], Bh[2], Bh[3]); \
            } \
        } \
    } }

    // prologue: B part of step-0 chunk 0 (mirrors steady-state pre-sync prefetch)
    LOAD_B_PART(0, 0);
    CP_COMMIT();

    for (int t = 0; t < NT; t++) {
        const int hb = t & 1, nb = hb ^ 1;
        const char* A_P = (const char*)g_hb[hb] + (size_t)brow0 * 1024;

        // A part of chunk 0 (h is ready after the previous cluster sync)
        LOAD_A_PART(0, 0, A_P);
        CP_COMMIT();

        // accumulator init from packed x_proj (overlaps chunk-0 load)
        {
            const float4* xp = (const float4*)(g_xpP + ((size_t)blockIdx.x * 256 + tid) * 64);
#pragma unroll
            for (int ie = 0; ie < 4; ie++) {
                const int i = ie >> 1, e0 = (ie & 1) * 2;
#pragma unroll
                for (int g = 0; g < 4; g++) {
                    float4 v = __ldg(&xp[ie * 4 + g]);
                    acc[i][g * 2 + 0][e0]     = v.x;
                    acc[i][g * 2 + 0][e0 + 1] = v.y;
                    acc[i][g * 2 + 1][e0]     = v.z;
                    acc[i][g * 2 + 1][e0 + 1] = v.w;
                }
            }
        }

        for (int kc = 0; kc < 8; kc++) {
            if (kc < 7) {
                LOAD_A_PART(kc + 1, (kc + 1) & 1, A_P);
                LOAD_B_PART(kc + 1, (kc + 1) & 1);
                CP_COMMIT();
            }
            if (kc < 7) CP_WAIT1(); else CP_WAIT0();
            __syncthreads();
            COMPUTE_CHUNK(kc & 1);
            __syncthreads();
        }

        // ---- epilogue: gates via tanh.approx -> c,h ; h stored fp16 ----
#pragma unroll
        for (int i = 0; i < 2; i++)
#pragma unroll
            for (int eh = 0; eh < 2; eh++) {
                const int b = brow0 + wm * 32 + i * 16 + frow + eh * 8;
                const int U = rank * 64 + u0w + fcol;
#pragma unroll
                for (int u8 = 0; u8 < 2; u8++) {
                    float h2[2];
#pragma unroll
                    for (int p = 0; p < 2; p++) {
                        const int e = eh * 2 + p;
                        float iv = sigA (acc[i][0 + u8][e]);
                        float fv = sigA (acc[i][2 + u8][e]);
                        float gv = tanhA(acc[i][4 + u8][e]);
                        float ov = sigA (acc[i][6 + u8][e]);
                        float cc = fv * cst[i][u8][e] + iv * gv;
                        cst[i][u8][e] = cc;
                        h2[p] = ov * tanhA(cc);
                    }
                    const int Uu = U + u8 * 8;
                    *(float2*)&g_hist[((size_t)t * NB + b) * NH + Uu] =
                        make_float2(h2[0], h2[1]);
                    *(uint32_t*)((char*)g_hb[nb] + (size_t)b * 1024 + Uu * 2) =
                        pack_h2(h2[0], h2[1]);
                }
            }

        // prefetch next step's B chunk 0 (h-independent) before the sync;
        // stage 0 is dead since kc=6's trailing barrier
        LOAD_B_PART(0, 0);
        CP_COMMIT();

        __threadfence();
        CLUSTER_SYNC();
    }
#undef LOAD_A_PART
#undef LOAD_B_PART
#undef COMPUTE_CHUNK
}

// ---------------------------------------------------------------------------
// Inputs: z, W_ih, W_hh, b_ih, b_hh, W_out, b_out, seq_len
// ---------------------------------------------------------------------------
extern "C" void kernel_launch(void* const* d_in, const int* in_sizes, int n_in,
                              void* d_out, int out_size)
{
    (void)in_sizes; (void)n_in; (void)out_size;
    const float* z    = (const float*)d_in[0];
    const float* Wih  = (const float*)d_in[1];
    const float* Whh  = (const float*)d_in[2];
    const float* bih  = (const float*)d_in[3];
    const float* bhh  = (const float*)d_in[4];
    const float* Wout = (const float*)d_in[5];
    const float* bout = (const float*)d_in[6];
    float* out = (float*)d_out;

    xproj_kernel <<<dim3(N4H / 256, NB / 16), 256>>>(z, Wih, bih, bhh);
    xpack_kernel <<<256, 256>>>();
    whalf_kernel <<<(N4H * NH) / 256, 256>>>(Whh);

    cudaFuncSetAttribute(lstm_mma_kernel, cudaFuncAttributeMaxDynamicSharedMemorySize,
                         SMEM_TOTAL);
    lstm_mma_kernel<<<256, TPB, SMEM_TOTAL>>>();

    outproj_kernel<<<(NT * NB) / 16, 128>>>(Wout, bout, out);
}